// round 4
// baseline (speedup 1.0000x reference)
#include <cuda_runtime.h>

// Problem constants (shapes fixed by setup_inputs)
#define NMAX   50000
#define EAMAX  850000     // E + N self loops
#define F_IN   128
#define HC     256        // heads*out_ch layer 1
#define H1     4
#define CH1    64         // agg1 edge chunk

// gemm tiling
#define BM 128
#define BN 128
#define BK 16
#define ASTRIDE 260       // floats per As2 row: 2*BM + 4 pad (16B-aligned, de-conflicts stores)

typedef unsigned long long u64;

// ---------------- scratch (static __device__, allocation-free) ----------------
__device__ float    g_h1[NMAX * HC];
__device__ float    g_Wt[F_IN * HC];       // W1 transposed [k][c]
__device__ float    g_as1[NMAX * H1];
__device__ float    g_ad1[NMAX * H1];
__device__ int      g_src[EAMAX];
__device__ int      g_dst[EAMAX];
__device__ int      g_cnt[NMAX];
__device__ int      g_rowstart[NMAX];
__device__ int      g_fill[NMAX];
__device__ int      g_csr_src[EAMAX];
__device__ float    g_h2[NMAX * 2];
__device__ float    g_as2[NMAX];
__device__ float    g_ad2[NMAX];
__device__ int      g_is64;

// ---------------- helpers ----------------
__device__ __forceinline__ float lrelu(float x) { return x > 0.f ? x : 0.2f * x; }

__device__ __forceinline__ u64 pack2(float lo, float hi) {
    u64 r;
    asm("mov.b64 %0, {%1, %2};" : "=l"(r) : "f"(lo), "f"(hi));
    return r;
}
__device__ __forceinline__ void unpack2(u64 v, float& lo, float& hi) {
    asm("mov.b64 {%0, %1}, %2;" : "=f"(lo), "=f"(hi) : "l"(v));
}
__device__ __forceinline__ u64 fma2(u64 a, u64 b, u64 c) {
    u64 d;
    asm("fma.rn.f32x2 %0, %1, %2, %3;" : "=l"(d) : "l"(a), "l"(b), "l"(c));
    return d;
}

// ---------------- setup kernels ----------------
__global__ void detect_kernel(const void* ei, int twoE, long long N) {
    if (threadIdx.x != 0 || blockIdx.x != 0) return;
    const long long* p = (const long long*)ei;
    int ok = 1;
    int m = twoE < 64 ? twoE : 64;
    for (int i = 0; i < m; i++) {
        long long v = p[i];
        if (v < 0 || v >= N) { ok = 0; break; }
    }
    g_is64 = ok;
}

// split edge_index + add self loops + zero degree counters (fused)
__global__ void edges_kernel(const void* ei, int E, int N) {
    int i = blockIdx.x * blockDim.x + threadIdx.x;
    int twoE = 2 * E;
    if (i < N) g_cnt[i] = 0;
    if (i < twoE) {
        int v;
        if (g_is64) v = (int)((const long long*)ei)[i];
        else        v = ((const int*)ei)[i];
        if (i < E) g_src[i] = v;
        else       g_dst[i - E] = v;
    } else if (i < twoE + N) {
        int n = i - twoE;
        g_src[E + n] = n;
        g_dst[E + n] = n;
    }
}

__global__ void wt_kernel(const float* __restrict__ W1) {
    int i = blockIdx.x * blockDim.x + threadIdx.x;
    if (i < F_IN * HC) {
        int k = i / HC, c = i % HC;
        g_Wt[i] = W1[c * F_IN + k];
    }
}

__global__ void hist_kernel(int EA) {
    int e = blockIdx.x * blockDim.x + threadIdx.x;
    if (e < EA) atomicAdd(&g_cnt[g_dst[e]], 1);
}

__global__ void scan_kernel(int N) {
    int t = threadIdx.x;
    int chunk = (N + 1023) >> 10;
    int lo = t * chunk;
    int hi = lo + chunk; if (hi > N) hi = N;
    int sum = 0;
    for (int i = lo; i < hi; i++) sum += g_cnt[i];
    __shared__ int sp[1024];
    sp[t] = sum;
    __syncthreads();
    for (int off = 1; off < 1024; off <<= 1) {
        int v = (t >= off) ? sp[t - off] : 0;
        __syncthreads();
        sp[t] += v;
        __syncthreads();
    }
    int run = sp[t] - sum;
    for (int i = lo; i < hi; i++) {
        g_rowstart[i] = run;
        g_fill[i]     = run;
        run += g_cnt[i];
    }
}

__global__ void scatter_kernel(int EA) {
    int e = blockIdx.x * blockDim.x + threadIdx.x;
    if (e >= EA) return;
    int d = g_dst[e];
    int pos = atomicAdd(&g_fill[d], 1);
    g_csr_src[pos] = g_src[e];
}

// ------------- h1 = x @ W1^T : register-tiled 128x128, f32x2, pair-duplicated A
__global__ void __launch_bounds__(256, 2) gemm1_kernel(const float* __restrict__ x, int N) {
    __shared__ float As2[BK * ASTRIDE];   // [k][2n] duplicated pairs {v,v}, padded
    __shared__ float Ws[BK * BN];         // [k][c]
    int t  = threadIdx.x;
    int tx = t & 15;          // col group: cols c0 + tx*8 .. +8
    int ty = t >> 4;          // node group: nodes n0 + ty*8 .. +8
    int n0 = blockIdx.x * BM;
    int c0 = blockIdx.y * BN;

    u64 acc[8][4];
#pragma unroll
    for (int i = 0; i < 8; i++)
#pragma unroll
        for (int j = 0; j < 4; j++) acc[i][j] = 0ull;

    for (int k0 = 0; k0 < F_IN; k0 += BK) {
        if (k0) __syncthreads();
        // stage A chunk transposed + duplicated: As2[k][2n]={v,v}
#pragma unroll
        for (int i = 0; i < 2; i++) {
            int lin  = t + 256 * i;        // 0..511 = 128 nodes x 4 kquads
            int node = lin >> 2;
            int kq   = lin & 3;
            float4 v = make_float4(0.f, 0.f, 0.f, 0.f);
            if (n0 + node < N)
                v = *(const float4*)&x[(n0 + node) * F_IN + k0 + kq * 4];
            float* dst = &As2[(kq * 4) * ASTRIDE + 2 * node];
            *(u64*)(dst + 0 * ASTRIDE) = pack2(v.x, v.x);
            *(u64*)(dst + 1 * ASTRIDE) = pack2(v.y, v.y);
            *(u64*)(dst + 2 * ASTRIDE) = pack2(v.z, v.z);
            *(u64*)(dst + 3 * ASTRIDE) = pack2(v.w, v.w);
        }
        // stage W chunk direct
#pragma unroll
        for (int i = 0; i < 2; i++) {
            int lin = t + 256 * i;         // 0..511 = 16 k x 32 cquads
            int k   = lin >> 5;
            int cq  = lin & 31;
            *(float4*)&Ws[k * BN + cq * 4] =
                *(const float4*)&g_Wt[(k0 + k) * HC + c0 + cq * 4];
        }
        __syncthreads();
#pragma unroll
        for (int k = 0; k < BK; k++) {
            const ulonglong2* ap = (const ulonglong2*)&As2[k * ASTRIDE + ty * 16];
            const ulonglong2* wq = (const ulonglong2*)&Ws[k * BN + tx * 8];
            ulonglong2 A0 = ap[0], A1 = ap[1], A2 = ap[2], A3 = ap[3];
            ulonglong2 W0 = wq[0], W1 = wq[1];
            u64 av[8] = {A0.x, A0.y, A1.x, A1.y, A2.x, A2.y, A3.x, A3.y};
            u64 wv[4] = {W0.x, W0.y, W1.x, W1.y};
#pragma unroll
            for (int i = 0; i < 8; i++)
#pragma unroll
                for (int j = 0; j < 4; j++)
                    acc[i][j] = fma2(wv[j], av[i], acc[i][j]);
        }
    }
    // store
#pragma unroll
    for (int i = 0; i < 8; i++) {
        int node = n0 + ty * 8 + i;
        if (node >= N) break;
        float4 f0, f1;
        unpack2(acc[i][0], f0.x, f0.y);
        unpack2(acc[i][1], f0.z, f0.w);
        unpack2(acc[i][2], f1.x, f1.y);
        unpack2(acc[i][3], f1.z, f1.w);
        float* o = &g_h1[node * HC + c0 + tx * 8];
        *(float4*)(o + 0) = f0;
        *(float4*)(o + 4) = f1;
    }
}

// per-node attention dots
__global__ void attdot1_kernel(const float* __restrict__ att_src,
                               const float* __restrict__ att_dst, int N) {
    int n = blockIdx.x;
    int t = threadIdx.x;  // 256
    float v = g_h1[n * HC + t];
    float s = v * att_src[t];
    float d = v * att_dst[t];
#pragma unroll
    for (int o = 16; o; o >>= 1) {
        s += __shfl_down_sync(0xFFFFFFFFu, s, o);
        d += __shfl_down_sync(0xFFFFFFFFu, d, o);
    }
    __shared__ float ss[8], dd[8];
    if ((t & 31) == 0) { ss[t >> 5] = s; dd[t >> 5] = d; }
    __syncthreads();
    if (t < H1) {
        g_as1[n * H1 + t] = ss[2 * t] + ss[2 * t + 1];
        g_ad1[n * H1 + t] = dd[2 * t] + dd[2 * t + 1];
    }
}

// ---- fused layer-1 softmax+aggregation+layer-2 projection: float4 gather ----
// 256 threads = 4 edge-groups x 64 float4 channel-lanes.
__global__ void agg1_kernel(const float* __restrict__ b1,
                            const float* __restrict__ W2,
                            const float* __restrict__ att_src2,
                            const float* __restrict__ att_dst2) {
    int n  = blockIdx.x;
    int t  = threadIdx.x;
    int g  = t >> 6;        // edge group 0..3
    int c4 = t & 63;        // float4 channel index
    int h4 = c4 >> 4;       // head of channels c4*4..+3
    int start = g_rowstart[n];
    int deg   = g_cnt[n];

    __shared__ float  sden[4];
    __shared__ float  sad[4];
    __shared__ int    ssrc[CH1];
    __shared__ float  sex[CH1 * 4];
    __shared__ float4 sacc4[256];
    __shared__ float  sr0[8], sr1[8];

    if (t < 4) { sden[t] = 0.f; sad[t] = g_ad1[n * 4 + t]; }
    __syncthreads();

    float4 acc = make_float4(0.f, 0.f, 0.f, 0.f);
    int ec = t >> 2, hh = t & 3;
    for (int e0 = 0; e0 < deg; e0 += CH1) {
        int csz = deg - e0; if (csz > CH1) csz = CH1;
        // exp phase: thread t = (edge ec, head hh)
        float ex = 0.f;
        if (ec < csz) {
            int s = g_csr_src[start + e0 + ec];
            if (hh == 0) ssrc[ec] = s;
            ex = __expf(lrelu(g_as1[s * 4 + hh] + sad[hh]));
        }
        sex[t] = ex;
        float p = ex;
        p += __shfl_down_sync(0xFFFFFFFFu, p, 16);
        p += __shfl_down_sync(0xFFFFFFFFu, p, 8);
        p += __shfl_down_sync(0xFFFFFFFFu, p, 4);
        if ((t & 31) < 4) atomicAdd(&sden[hh], p);
        __syncthreads();
        // gather phase: group g handles edges e = g, g+4, ... (4 edges in flight)
        for (int e = g; e < csz; e += 4) {
            int s = ssrc[e];
            float coef = sex[e * 4 + h4];
            float4 v = *(const float4*)&g_h1[s * HC + c4 * 4];
            acc.x += coef * v.x;
            acc.y += coef * v.y;
            acc.z += coef * v.z;
            acc.w += coef * v.w;
        }
        __syncthreads();
    }
    sacc4[t] = acc;
    __syncthreads();

    // combine groups: flat float index g*256 + c  (c = channel = t)
    const float* sp = (const float*)sacc4;
    float y = sp[t] + sp[256 + t] + sp[512 + t] + sp[768 + t];
    int h = t >> 6;
    y = y / (sden[h] + 1e-16f) + b1[t];
    y = fmaxf(y, 0.f);

    float p0 = y * W2[t];
    float p1 = y * W2[HC + t];
#pragma unroll
    for (int o = 16; o; o >>= 1) {
        p0 += __shfl_down_sync(0xFFFFFFFFu, p0, o);
        p1 += __shfl_down_sync(0xFFFFFFFFu, p1, o);
    }
    if ((t & 31) == 0) { sr0[t >> 5] = p0; sr1[t >> 5] = p1; }
    __syncthreads();
    if (t == 0) {
        float a0 = 0.f, a1 = 0.f;
#pragma unroll
        for (int w = 0; w < 8; w++) { a0 += sr0[w]; a1 += sr1[w]; }
        g_h2[n * 2 + 0] = a0;
        g_h2[n * 2 + 1] = a1;
        g_as2[n] = a0 * att_src2[0] + a1 * att_src2[1];
        g_ad2[n] = a0 * att_dst2[0] + a1 * att_dst2[1];
    }
}

// ---------------- fused layer-2: one warp per destination node --------------
__global__ void agg2_kernel(const float* __restrict__ b2,
                            float* __restrict__ out, int N) {
    int gid  = blockIdx.x * blockDim.x + threadIdx.x;
    int n    = gid >> 5;
    int lane = gid & 31;
    if (n >= N) return;
    int start = g_rowstart[n];
    int deg   = g_cnt[n];
    float adv = g_ad2[n];

    float den = 0.f, a0 = 0.f, a1 = 0.f;
    for (int e = lane; e < deg; e += 32) {
        int s  = g_csr_src[start + e];
        float ex = __expf(lrelu(g_as2[s] + adv));
        den += ex;
        float2 hv = *(const float2*)&g_h2[s * 2];
        a0 += ex * hv.x;
        a1 += ex * hv.y;
    }
#pragma unroll
    for (int o = 16; o; o >>= 1) {
        den += __shfl_xor_sync(0xFFFFFFFFu, den, o);
        a0  += __shfl_xor_sync(0xFFFFFFFFu, a0, o);
        a1  += __shfl_xor_sync(0xFFFFFFFFu, a1, o);
    }
    if (lane == 0) {
        float inv = 1.f / (den + 1e-16f);
        out[n * 2 + 0] = a0 * inv + b2[0];
        out[n * 2 + 1] = a1 * inv + b2[1];
    }
}

// ---------------- launch ----------------
extern "C" void kernel_launch(void* const* d_in, const int* in_sizes, int n_in,
                              void* d_out, int out_size) {
    const float* x        = (const float*)d_in[0];
    const void*  ei       = d_in[1];
    const float* W1       = (const float*)d_in[2];
    const float* att_src1 = (const float*)d_in[3];
    const float* att_dst1 = (const float*)d_in[4];
    const float* b1       = (const float*)d_in[5];
    const float* W2       = (const float*)d_in[6];
    const float* att_src2 = (const float*)d_in[7];
    const float* att_dst2 = (const float*)d_in[8];
    const float* b2       = (const float*)d_in[9];

    int N  = in_sizes[0] / F_IN;
    int E  = in_sizes[1] / 2;
    int EA = E + N;

    const int B = 256;
    int gE = (EA + B - 1) / B;

    detect_kernel<<<1, 32>>>(ei, 2 * E, (long long)N);               // idx 0
    edges_kernel<<<(2 * E + N + B - 1) / B, B>>>(ei, E, N);          // idx 1
    wt_kernel<<<(F_IN * HC + B - 1) / B, B>>>(W1);                   // idx 2

    dim3 gg((N + BM - 1) / BM, HC / BN);
    gemm1_kernel<<<gg, 256>>>(x, N);                                 // idx 3 (profiled)

    hist_kernel<<<gE, B>>>(EA);                                      // idx 4
    scan_kernel<<<1, 1024>>>(N);                                     // idx 5
    scatter_kernel<<<gE, B>>>(EA);                                   // idx 6

    attdot1_kernel<<<N, 256>>>(att_src1, att_dst1, N);               // idx 7
    agg1_kernel<<<N, 256>>>(b1, W2, att_src2, att_dst2);             // idx 8
    agg2_kernel<<<(N * 32 + B - 1) / B, B>>>(b2, (float*)d_out, N);  // idx 9
}